// round 1
// baseline (speedup 1.0000x reference)
#include <cuda_runtime.h>
#include <math.h>

// ---------------------------------------------------------------------------
// RandomProjection: out[b,o] = mean_s( cos(x[b,s,:], p[o,:]) )
// Restructured: m[b,:] = mean_s( x[b,s,:]/max(||x||,eps) )  (kernel B)
//               out[b,o] = m[b,:] . p[o,:] / max(||p[o]||,eps)  (kernel C)
// ---------------------------------------------------------------------------

#define B_   32
#define S_   512
#define D_   768
#define O_   2048
#define EPS_ 1e-8f

// scratch: mean of normalized token embeddings, [B, D]
__device__ float g_m[B_ * D_];

// ---------------------------------------------------------------------------
// Kernel A: zero the scratch accumulator (needed every replay; atomics follow)
// ---------------------------------------------------------------------------
__global__ void zero_m_kernel() {
    int i = blockIdx.x * blockDim.x + threadIdx.x;
    if (i < B_ * D_) g_m[i] = 0.0f;
}

// ---------------------------------------------------------------------------
// Kernel B: normalize rows of x, accumulate mean into g_m.
// One warp handles ROWS_PER_WARP consecutive s-rows of one batch b.
// Row = 768 floats = 192 float4; each lane owns 6 float4 (indices lane+32c).
// ---------------------------------------------------------------------------
#define ROWS_PER_WARP 8
#define GROUPS_PER_B  (S_ / ROWS_PER_WARP)   // 64

__global__ void __launch_bounds__(256, 8)
reduce_x_kernel(const float* __restrict__ x) {
    const int warp_global = (blockIdx.x * blockDim.x + threadIdx.x) >> 5;
    const int lane        = threadIdx.x & 31;

    const int b  = warp_global / GROUPS_PER_B;
    const int sg = warp_global % GROUPS_PER_B;
    if (b >= B_) return;

    const float inv_S = 1.0f / (float)S_;

    float4 acc[6];
    #pragma unroll
    for (int c = 0; c < 6; c++) acc[c] = make_float4(0.f, 0.f, 0.f, 0.f);

    #pragma unroll
    for (int r = 0; r < ROWS_PER_WARP; r++) {
        const int s = sg * ROWS_PER_WARP + r;
        const float4* row = reinterpret_cast<const float4*>(
            x + ((size_t)b * S_ + s) * D_);

        float4 v[6];
        #pragma unroll
        for (int c = 0; c < 6; c++) v[c] = row[lane + 32 * c];

        // sum of squares for this row
        float ss = 0.f;
        #pragma unroll
        for (int c = 0; c < 6; c++) {
            ss += v[c].x * v[c].x + v[c].y * v[c].y
                + v[c].z * v[c].z + v[c].w * v[c].w;
        }
        #pragma unroll
        for (int off = 16; off > 0; off >>= 1)
            ss += __shfl_xor_sync(0xFFFFFFFFu, ss, off);

        const float scale = inv_S / fmaxf(sqrtf(ss), EPS_);

        #pragma unroll
        for (int c = 0; c < 6; c++) {
            acc[c].x += v[c].x * scale;
            acc[c].y += v[c].y * scale;
            acc[c].z += v[c].z * scale;
            acc[c].w += v[c].w * scale;
        }
    }

    float* m = g_m + b * D_;
    #pragma unroll
    for (int c = 0; c < 6; c++) {
        const int d = (lane + 32 * c) * 4;
        atomicAdd(m + d + 0, acc[c].x);
        atomicAdd(m + d + 1, acc[c].y);
        atomicAdd(m + d + 2, acc[c].z);
        atomicAdd(m + d + 3, acc[c].w);
    }
}

// ---------------------------------------------------------------------------
// Kernel C: out[b,o] = (m[b,:] . p[o,:]) / max(||p[o]||, eps)
// 128 blocks x 128 threads; each block: 16 o-rows, full m staged in smem.
// Each warp handles 4 o-rows sequentially; 32 accumulators per lane (one per b).
// ---------------------------------------------------------------------------
#define O_PER_BLOCK 16
#define O_PER_WARP  4

__global__ void __launch_bounds__(128, 2)
gemm_kernel(const float* __restrict__ p, float* __restrict__ out) {
    extern __shared__ float ms[];   // B_*D_ = 24576 floats = 96 KB

    // stage m into shared: 6144 float4, 128 threads -> 48 each
    {
        const float4* src = reinterpret_cast<const float4*>(g_m);
        float4*       dst = reinterpret_cast<float4*>(ms);
        for (int i = threadIdx.x; i < (B_ * D_) / 4; i += blockDim.x)
            dst[i] = src[i];
    }
    __syncthreads();

    const int warp = threadIdx.x >> 5;
    const int lane = threadIdx.x & 31;
    const int o0   = blockIdx.x * O_PER_BLOCK + warp * O_PER_WARP;

    #pragma unroll 1
    for (int i = 0; i < O_PER_WARP; i++) {
        const int o = o0 + i;
        const float4* prow = reinterpret_cast<const float4*>(p + (size_t)o * D_);

        float4 v[6];
        #pragma unroll
        for (int c = 0; c < 6; c++) v[c] = prow[lane + 32 * c];

        float ss = 0.f;
        #pragma unroll
        for (int c = 0; c < 6; c++) {
            ss += v[c].x * v[c].x + v[c].y * v[c].y
                + v[c].z * v[c].z + v[c].w * v[c].w;
        }
        #pragma unroll
        for (int off = 16; off > 0; off >>= 1)
            ss += __shfl_xor_sync(0xFFFFFFFFu, ss, off);
        const float rnorm = 1.0f / fmaxf(sqrtf(ss), EPS_);

        float acc[B_];
        #pragma unroll
        for (int b = 0; b < B_; b++) acc[b] = 0.f;

        #pragma unroll
        for (int b = 0; b < B_; b++) {
            const float4* mb = reinterpret_cast<const float4*>(ms + b * D_);
            #pragma unroll
            for (int c = 0; c < 6; c++) {
                const float4 mv = mb[lane + 32 * c];
                acc[b] += mv.x * v[c].x;
                acc[b] += mv.y * v[c].y;
                acc[b] += mv.z * v[c].z;
                acc[b] += mv.w * v[c].w;
            }
        }

        // reduce each acc[b] across lanes; lane==b writes its result
        #pragma unroll
        for (int b = 0; b < B_; b++) {
            float a = acc[b];
            #pragma unroll
            for (int off = 16; off > 0; off >>= 1)
                a += __shfl_xor_sync(0xFFFFFFFFu, a, off);
            if (lane == b) out[(size_t)b * O_ + o] = a * rnorm;
        }
    }
}

// ---------------------------------------------------------------------------
extern "C" void kernel_launch(void* const* d_in, const int* in_sizes, int n_in,
                              void* d_out, int out_size) {
    const float* x = (const float*)d_in[0];   // [32, 512, 768]
    const float* p = (const float*)d_in[1];   // [2048, 768]
    float*     out = (float*)d_out;           // [32, 2048]

    (void)in_sizes; (void)n_in; (void)out_size;

    static bool smem_attr_set = false;
    if (!smem_attr_set) {
        cudaFuncSetAttribute(gemm_kernel,
                             cudaFuncAttributeMaxDynamicSharedMemorySize,
                             B_ * D_ * (int)sizeof(float));
        smem_attr_set = true;
    }

    // A: zero accumulator
    zero_m_kernel<<<(B_ * D_ + 255) / 256, 256>>>();

    // B: normalize + reduce x -> g_m   (2048 warps = 256 blocks x 8 warps)
    const int total_warps = B_ * GROUPS_PER_B;           // 2048
    reduce_x_kernel<<<total_warps / 8, 256>>>(x);

    // C: projected GEMM with on-the-fly p normalization
    gemm_kernel<<<O_ / O_PER_BLOCK, 128, B_ * D_ * (int)sizeof(float)>>>(p, out);
}

// round 2
// speedup vs baseline: 2.1750x; 2.1750x over previous
#include <cuda_runtime.h>
#include <math.h>

// ---------------------------------------------------------------------------
// RandomProjection: out[b,o] = mean_s( cos(x[b,s,:], p[o,:]) )
//   m[b,:] = mean_s( x[b,s,:] / max(||x[b,s]||, eps) )      (kernel 1, partials)
//   out[b,o] = (m[b,:] . p[o,:]) / max(||p[o]||, eps)       (kernel 2)
// ---------------------------------------------------------------------------

#define B_   32
#define S_   512
#define D_   768
#define O_   2048
#define EPS_ 1e-8f
#define PQ_  4            // partials per batch (s split in 4 quarters)

// race-free partials: [PQ][B][D]; fully overwritten every call (no init needed)
__device__ float g_part[PQ_ * B_ * D_];

// ---------------------------------------------------------------------------
// Kernel 1: per-row normalize + partial sequence-mean.
// Grid: 128 blocks = (b, quarter q). Block: 512 threads = 16 warps.
// Each warp: 8 consecutive s-rows, software-prefetched 1 row deep.
// Block tree-reduce in smem, single plain store to g_part (no atomics).
// ---------------------------------------------------------------------------
__global__ void __launch_bounds__(512, 1)
reduce_x_kernel(const float* __restrict__ x) {
    __shared__ float4 sm[16 * 192];   // 16 warps x 192 float4 = 48 KB

    const int q    = blockIdx.x & 3;
    const int b    = blockIdx.x >> 2;
    const int warp = threadIdx.x >> 5;
    const int lane = threadIdx.x & 31;

    // rows handled by this warp: s = q*128 + warp*8 + r
    const float4* base = reinterpret_cast<const float4*>(
        x + ((size_t)b * S_ + (size_t)q * 128 + (size_t)warp * 8) * D_);

    const float inv_S = 1.0f / (float)S_;

    float4 acc[6];
    #pragma unroll
    for (int c = 0; c < 6; c++) acc[c] = make_float4(0.f, 0.f, 0.f, 0.f);

    float4 v[6];
    #pragma unroll
    for (int c = 0; c < 6; c++) v[c] = base[lane + 32 * c];

    #pragma unroll
    for (int r = 0; r < 8; r++) {
        float4 vn[6];
        if (r < 7) {
            #pragma unroll
            for (int c = 0; c < 6; c++)
                vn[c] = base[(r + 1) * 192 + lane + 32 * c];
        }

        float ss = 0.f;
        #pragma unroll
        for (int c = 0; c < 6; c++)
            ss += v[c].x * v[c].x + v[c].y * v[c].y
                + v[c].z * v[c].z + v[c].w * v[c].w;
        #pragma unroll
        for (int off = 16; off > 0; off >>= 1)
            ss += __shfl_xor_sync(0xFFFFFFFFu, ss, off);

        const float scale = inv_S / fmaxf(sqrtf(ss), EPS_);

        #pragma unroll
        for (int c = 0; c < 6; c++) {
            acc[c].x += v[c].x * scale;
            acc[c].y += v[c].y * scale;
            acc[c].z += v[c].z * scale;
            acc[c].w += v[c].w * scale;
        }

        if (r < 7) {
            #pragma unroll
            for (int c = 0; c < 6; c++) v[c] = vn[c];
        }
    }

    #pragma unroll
    for (int c = 0; c < 6; c++)
        sm[warp * 192 + lane + 32 * c] = acc[c];
    __syncthreads();

    // first 192 threads: sum 16 warp partials, store to g_part[q][b][:]
    if (threadIdx.x < 192) {
        float4 s = sm[threadIdx.x];
        #pragma unroll
        for (int w = 1; w < 16; w++) {
            const float4 t = sm[w * 192 + threadIdx.x];
            s.x += t.x; s.y += t.y; s.z += t.z; s.w += t.w;
        }
        reinterpret_cast<float4*>(g_part)[((q * B_ + b) * 192) + threadIdx.x] = s;
    }
}

// ---------------------------------------------------------------------------
// Kernel 2: out[b,o] = (m[b,:] . p[o,:]) / max(||p[o]||, eps)
// Grid: 128 blocks x 256 threads. Staging combines the 4 partials into smem.
// Each warp handles 2 o-rows simultaneously (each m element feeds 2 FFMAs).
// ---------------------------------------------------------------------------
__global__ void __launch_bounds__(256, 1)
gemm_kernel(const float* __restrict__ p, float* __restrict__ out) {
    extern __shared__ float ms[];   // B_*D_ = 24576 floats = 96 KB

    // stage m = sum of 4 partials (6144 float4)
    {
        const float4* gp = reinterpret_cast<const float4*>(g_part);
        float4*      dst = reinterpret_cast<float4*>(ms);
        for (int i = threadIdx.x; i < (B_ * D_) / 4; i += 256) {
            float4 a = gp[i];
            const float4 b4 = gp[6144  + i];
            const float4 c4 = gp[12288 + i];
            const float4 d4 = gp[18432 + i];
            a.x += b4.x + c4.x + d4.x;
            a.y += b4.y + c4.y + d4.y;
            a.z += b4.z + c4.z + d4.z;
            a.w += b4.w + c4.w + d4.w;
            dst[i] = a;
        }
    }
    __syncthreads();

    const int warp = threadIdx.x >> 5;
    const int lane = threadIdx.x & 31;
    const int o0   = blockIdx.x * 16 + warp * 2;   // 2 o-rows per warp

    // load both p rows into registers
    float4 v[2][6];
    #pragma unroll
    for (int oo = 0; oo < 2; oo++) {
        const float4* prow = reinterpret_cast<const float4*>(p + (size_t)(o0 + oo) * D_);
        #pragma unroll
        for (int c = 0; c < 6; c++) v[oo][c] = prow[lane + 32 * c];
    }

    // norms of both p rows
    float rn[2];
    #pragma unroll
    for (int oo = 0; oo < 2; oo++) {
        float ss = 0.f;
        #pragma unroll
        for (int c = 0; c < 6; c++)
            ss += v[oo][c].x * v[oo][c].x + v[oo][c].y * v[oo][c].y
                + v[oo][c].z * v[oo][c].z + v[oo][c].w * v[oo][c].w;
        #pragma unroll
        for (int off = 16; off > 0; off >>= 1)
            ss += __shfl_xor_sync(0xFFFFFFFFu, ss, off);
        rn[oo] = 1.0f / fmaxf(sqrtf(ss), EPS_);
    }

    float acc0[B_], acc1[B_];
    #pragma unroll
    for (int b = 0; b < B_; b++) { acc0[b] = 0.f; acc1[b] = 0.f; }

    #pragma unroll
    for (int b = 0; b < B_; b++) {
        const float4* mb = reinterpret_cast<const float4*>(ms + b * D_);
        #pragma unroll
        for (int c = 0; c < 6; c++) {
            const float4 mv = mb[lane + 32 * c];
            acc0[b] += mv.x * v[0][c].x + mv.y * v[0][c].y
                     + mv.z * v[0][c].z + mv.w * v[0][c].w;
            acc1[b] += mv.x * v[1][c].x + mv.y * v[1][c].y
                     + mv.z * v[1][c].z + mv.w * v[1][c].w;
        }
    }

    // cross-lane reduce; lane==b writes both outputs for its batch
    #pragma unroll
    for (int b = 0; b < B_; b++) {
        float a0 = acc0[b], a1 = acc1[b];
        #pragma unroll
        for (int off = 16; off > 0; off >>= 1) {
            a0 += __shfl_xor_sync(0xFFFFFFFFu, a0, off);
            a1 += __shfl_xor_sync(0xFFFFFFFFu, a1, off);
        }
        if (lane == b) {
            out[(size_t)b * O_ + o0]     = a0 * rn[0];
            out[(size_t)b * O_ + o0 + 1] = a1 * rn[1];
        }
    }
}

// ---------------------------------------------------------------------------
extern "C" void kernel_launch(void* const* d_in, const int* in_sizes, int n_in,
                              void* d_out, int out_size) {
    const float* x = (const float*)d_in[0];   // [32, 512, 768]
    const float* p = (const float*)d_in[1];   // [2048, 768]
    float*     out = (float*)d_out;           // [32, 2048]

    (void)in_sizes; (void)n_in; (void)out_size;

    static bool attr_set = false;
    if (!attr_set) {
        cudaFuncSetAttribute(gemm_kernel,
                             cudaFuncAttributeMaxDynamicSharedMemorySize,
                             B_ * D_ * (int)sizeof(float));
        attr_set = true;
    }

    // Kernel 1: x -> 4 race-free partials of m
    reduce_x_kernel<<<B_ * PQ_, 512>>>(x);

    // Kernel 2: combine partials + projected GEMM
    gemm_kernel<<<O_ / 16, 256, B_ * D_ * (int)sizeof(float)>>>(p, out);
}